// round 4
// baseline (speedup 1.0000x reference)
#include <cuda_runtime.h>

#define NN 512
#define TP 16

typedef unsigned long long ull;

// ---------- f32x2 packed helpers (FFMA2: 2x fp32 rate, only reachable via PTX) ----------
__device__ __forceinline__ ull pk2(float lo, float hi) {
    ull r; asm("mov.b64 %0, {%1, %2};" : "=l"(r) : "f"(lo), "f"(hi)); return r;
}
__device__ __forceinline__ void upk2(float& lo, float& hi, ull v) {
    asm("mov.b64 {%0, %1}, %2;" : "=f"(lo), "=f"(hi) : "l"(v));
}
__device__ __forceinline__ void ffma2(ull& acc, ull a, ull b) {
    asm("fma.rn.f32x2 %0, %1, %2, %0;" : "+l"(acc) : "l"(a), "l"(b));
}

// ---------------- scratch ----------------
__device__ float g_XW1a[NN * TP * 32];
__device__ float g_XW1b[NN * TP * 32];
__device__ float g_XW2a[NN * TP * 32];
__device__ float g_XW2b[NN * TP * 32];
__device__ float g_Q[NN * 32];
__device__ float g_QB[NN * TP];
__device__ float g_RA[NN * TP];
__device__ float g_L1[NN * NN];    // logits1 -> s1
__device__ float g_L2T[NN * NN];   // logits2^T -> s2^T
__device__ float g_r1[NN * TP];
__device__ float g_c2[NN * TP];
__device__ float g_acc[NN * 32];

// ---------------- k1: XW1a/b, XW2a/b, Q, QB, RA ----------------
__global__ void k1_precompute(const float* __restrict__ x,
                              const float* __restrict__ W1,
                              const float* __restrict__ W2,
                              const float* __restrict__ W3) {
    int n0 = blockIdx.x * 4;
    __shared__ float xs[4][16];
    int tid = threadIdx.x;
    if (tid < 64) xs[tid / 16][tid % 16] = x[(n0 + tid / 16) * 16 + (tid % 16)];
    __syncthreads();

    for (int th = tid; th < 512; th += 256) {
        float a1[4] = {0,0,0,0}, b1[4] = {0,0,0,0};
        float a2[4] = {0,0,0,0}, b2[4] = {0,0,0,0};
        for (int i = 0; i < 16; i++) {
            float w1a = W1[i * 512 + th];
            float w1b = W1[(i + 16) * 512 + th];
            float w2a = W2[i * 512 + th];
            float w2b = W2[(i + 16) * 512 + th];
#pragma unroll
            for (int j = 0; j < 4; j++) {
                float xv = xs[j][i];
                a1[j] += xv * w1a; b1[j] += xv * w1b;
                a2[j] += xv * w2a; b2[j] += xv * w2b;
            }
        }
#pragma unroll
        for (int j = 0; j < 4; j++) {
            g_XW1a[(n0 + j) * 512 + th] = a1[j];
            g_XW1b[(n0 + j) * 512 + th] = b1[j];
            g_XW2a[(n0 + j) * 512 + th] = a2[j];
            g_XW2b[(n0 + j) * 512 + th] = b2[j];
        }
    }
    if (tid < 32) {
#pragma unroll
        for (int j = 0; j < 4; j++) {
            float acc = 0.f;
            for (int i = 0; i < 16; i++) acc += xs[j][i] * W3[i * 32 + tid];
            g_Q[(n0 + j) * 32 + tid] = acc;
        }
    }
    __syncthreads();
    if (tid < 64) {
        int n = n0 + tid / 16, t = tid % 16;
        const float* q  = g_Q + n * 32;
        const float* wa = g_XW1a + n * 512 + t * 32;
        const float* wb = g_XW1b + n * 512 + t * 32;
        float ra = 0.f, qb = 0.f;
#pragma unroll
        for (int h = 0; h < 32; h++) { float qv = q[h]; ra += qv * wa[h]; qb += qv * wb[h]; }
        g_RA[n * 16 + t] = ra;
        g_QB[n * 16 + t] = qb;
    }
}

// ---------------- k2: fused logits + zero accumulators ----------------
__global__ void __launch_bounds__(512) k2_logits(const float* __restrict__ adj) {
    int tid = threadIdx.x;
    int bid = blockIdx.y * 16 + blockIdx.x;
    if (bid < 32)      g_acc[bid * 512 + tid] = 0.f;
    else if (bid < 48) g_r1[(bid - 32) * 512 + tid] = 0.f;
    else if (bid < 64) g_c2[(bid - 48) * 512 + tid] = 0.f;

    int a0 = blockIdx.y * 32, b0 = blockIdx.x * 32;
    int bl = tid >> 4, t = tid & 15;
    int bg = b0 + bl;

    __shared__ ull   Qs[32][16];
    __shared__ float QBs[32][16], RAs[32][16];
    {
        int a = tid >> 4, p = tid & 15;
        float2 v = *((const float2*)(g_Q + (a0 + a) * 32) + p);
        Qs[a][p]  = pk2(v.x, v.y);
        QBs[a][p] = g_QB[(a0 + a) * 16 + p];
        RAs[a][p] = g_RA[(a0 + a) * 16 + p];
    }
    ull wa[16], wb[16];
    {
        const float4* pa = (const float4*)(g_XW1a + (bg * 16 + t) * 32);
        const float4* pb = (const float4*)(g_XW1b + (bg * 16 + t) * 32);
#pragma unroll
        for (int v = 0; v < 8; v++) {
            float4 fa = pa[v], fb = pb[v];
            wa[2 * v] = pk2(fa.x, fa.y); wa[2 * v + 1] = pk2(fa.z, fa.w);
            wb[2 * v] = pk2(fb.x, fb.y); wb[2 * v + 1] = pk2(fb.z, fb.w);
        }
    }
    __syncthreads();

    bool hasT = (t < 15);
    const float* pR = adj + ((long)a0 * 512 + bg) * 15 + t;
    const float* pC = adj + ((long)bg * 512 + a0) * 15 + t;

    for (int al = 0; al < 32; al++) {
        int ag = a0 + al;
        ull acc1 = 0ull, acc2 = 0ull;
        const ulonglong2* qrow = (const ulonglong2*)Qs[al];
#pragma unroll
        for (int j = 0; j < 8; j++) {
            ulonglong2 q = qrow[j];
            ffma2(acc1, q.x, wa[2 * j]);
            ffma2(acc1, q.y, wa[2 * j + 1]);
            ffma2(acc2, q.x, wb[2 * j]);
            ffma2(acc2, q.y, wb[2 * j + 1]);
        }
        float lo, hi;
        upk2(lo, hi, acc1); float p1 = lo + hi;
        upk2(lo, hi, acc2); float p2 = lo + hi;

        float l1p, l2p;
        if (hasT) {
            float ar = pR[al * 7680];
            float ac = pC[al * 15];
            l1p = ar * p1 + ac * QBs[al][t];
            l2p = ac * RAs[al][t] + ar * p2;
        } else {
            bool dg = (ag == bg);
            l1p = dg ? (p1 + QBs[al][15]) : 0.f;
            l2p = dg ? (RAs[al][15] + p2) : 0.f;
        }
#pragma unroll
        for (int o = 8; o; o >>= 1) {
            l1p += __shfl_xor_sync(0xffffffffu, l1p, o);
            l2p += __shfl_xor_sync(0xffffffffu, l2p, o);
        }
        if (t == 0) {
            g_L1[ag * 512 + bg]  = l1p;
            g_L2T[ag * 512 + bg] = l2p;
        }
    }
}

// ---------------- k5: row softmax ----------------
__global__ void k5_softmax() {
    int r = blockIdx.x;
    float* row = (r < 512) ? (g_L1 + r * 512) : (g_L2T + (r - 512) * 512);
    int tid = threadIdx.x;
    __shared__ float red[8];
    float v0 = row[tid], v1 = row[tid + 256];
    float m = fmaxf(v0, v1);
#pragma unroll
    for (int o = 16; o; o >>= 1) m = fmaxf(m, __shfl_xor_sync(0xffffffffu, m, o));
    if ((tid & 31) == 0) red[tid >> 5] = m;
    __syncthreads();
    float bm = red[0];
#pragma unroll
    for (int i = 1; i < 8; i++) bm = fmaxf(bm, red[i]);
    float e0 = __expf(v0 - bm), e1 = __expf(v1 - bm);
    float s = e0 + e1;
#pragma unroll
    for (int o = 16; o; o >>= 1) s += __shfl_xor_sync(0xffffffffu, s, o);
    __syncthreads();
    if ((tid & 31) == 0) red[tid >> 5] = s;
    __syncthreads();
    float bs = red[0] + red[1] + red[2] + red[3] + red[4] + red[5] + red[6] + red[7];
    float inv = 1.0f / bs;
    row[tid] = e0 * inv;
    row[tid + 256] = e1 * inv;
}

// ---------------- k7: split-variant fused A-build + register-blocked GEMM ----------------
// grid (16 m-tiles, 16 a-tiles, 2 variants), 256 threads.
// variant 0: acc += (s1*adj) @ XW2a, computes r1.  variant 1: acc += (s2t*adj) @ XW2b, computes c2.
struct K7S {
    ull   Asp[128][16];    // packed a-pairs
    float Bs[128][32];
    float ss[32][33];
    float adjS[32][121];
    float accS[32][33];
};

__global__ void __launch_bounds__(256) k7_fused(const float* __restrict__ adj) {
    extern __shared__ char smem_raw[];
    K7S& S = *reinterpret_cast<K7S*>(smem_raw);
    int m0 = blockIdx.x * 32;
    int a0 = blockIdx.y * 32;
    int var = blockIdx.z;
    int tid = threadIdx.x;

    const float* sSrc = var ? g_L2T : g_L1;
    const float* bSrc = var ? g_XW2b : g_XW2a;
    float* rcDst      = var ? g_c2 : g_r1;

#pragma unroll
    for (int j = 0; j < 4; j++) {
        int idx = tid + j * 256;
        int a = idx >> 5, ml = idx & 31;
        S.ss[a][ml] = sSrc[(a0 + a) * 512 + m0 + ml];
    }
    __syncthreads();

    // r1/c2 partials over this block's m-range
    {
        int a = tid >> 3, tp = tid & 7;
        int t0 = tp * 2;
        int ag = a0 + a;
        bool hasT1 = (t0 + 1 < 15);
        float r0 = 0.f, r1v = 0.f;
        for (int ml = 0; ml < 32; ml++) {
            const float* base = adj + ((long)(m0 + ml) * 512 + ag) * 15;
            float v0 = base[t0];
            float v1 = hasT1 ? base[t0 + 1] : 0.f;
            float w = S.ss[a][ml];
            r0 += w * v0; r1v += w * v1;
        }
        atomicAdd(&rcDst[ag * 16 + t0], r0);
        if (hasT1) {
            atomicAdd(&rcDst[ag * 16 + t0 + 1], r1v);
        } else if (ag >= m0 && ag < m0 + 32) {
            atomicAdd(&rcDst[ag * 16 + 15], S.ss[a][ag - m0]);
        }
    }

    // thread tile: 4a x 4d, 4-way k-split within block
    int pos = tid & 63, ksub = tid >> 6;
    int a4 = (pos & 7) * 4;
    int d4 = (pos >> 3) * 4;
    ull acc[2][4];
#pragma unroll
    for (int p = 0; p < 2; p++)
#pragma unroll
        for (int j = 0; j < 4; j++) acc[p][j] = 0ull;

    for (int mc = 0; mc < 4; mc++) {
        int mb = m0 + mc * 8;
        __syncthreads();
        // stage adj rows: 32 a x 120 contiguous floats
        for (int idx = tid; idx < 960; idx += 256) {
            int a = idx / 30, r4 = (idx - a * 30) * 4;
            float4 v = *(const float4*)(adj + (long)(a0 + a) * 7680 + mb * 15 + r4);
            float* dst = &S.adjS[a][r4];
            dst[0] = v.x; dst[1] = v.y; dst[2] = v.z; dst[3] = v.w;
        }
        // stage B panel (float4)
        for (int idx = tid; idx < 1024; idx += 256) {
            int kk = idx >> 3, dd = (idx & 7) * 4;
            *(float4*)&S.Bs[kk][dd] = *(const float4*)(bSrc + (mb * 16 + kk) * 32 + dd);
        }
        __syncthreads();
        // build packed A tile
#pragma unroll
        for (int j = 0; j < 8; j++) {
            int idx = tid + j * 256;
            int ap = idx & 15, kk = idx >> 4;
            int ml = kk >> 4, t = kk & 15;
            float v[2];
#pragma unroll
            for (int l = 0; l < 2; l++) {
                int a = 2 * ap + l;
                float sv = S.ss[a][mc * 8 + ml];
                if (t < 15) {
                    v[l] = sv * S.adjS[a][ml * 15 + t];
                } else {
                    v[l] = (mb + ml == a0 + a) ? sv : 0.f;
                }
            }
            S.Asp[kk][ap] = pk2(v[0], v[1]);
        }
        __syncthreads();
        // inner: 32 kk per thread
        int kk0 = ksub * 32;
        const ull*   pA = &S.Asp[0][(pos & 7) * 2];
        const float* pB = &S.Bs[0][d4];
#pragma unroll 8
        for (int kk = kk0; kk < kk0 + 32; kk++) {
            ulonglong2 A = *(const ulonglong2*)(pA + kk * 16);
            float4 b = *(const float4*)(pB + kk * 32);
            ull bx = pk2(b.x, b.x), by = pk2(b.y, b.y);
            ull bz = pk2(b.z, b.z), bw = pk2(b.w, b.w);
            ffma2(acc[0][0], A.x, bx); ffma2(acc[0][1], A.x, by);
            ffma2(acc[0][2], A.x, bz); ffma2(acc[0][3], A.x, bw);
            ffma2(acc[1][0], A.y, bx); ffma2(acc[1][1], A.y, by);
            ffma2(acc[1][2], A.y, bz); ffma2(acc[1][3], A.y, bw);
        }
    }

    // merge 4 k-split partials in smem (pass 0 writes, 1-3 add)
    for (int s = 0; s < 4; s++) {
        __syncthreads();
        if (ksub == s) {
#pragma unroll
            for (int p = 0; p < 2; p++)
#pragma unroll
                for (int j = 0; j < 4; j++) {
                    float lo, hi; upk2(lo, hi, acc[p][j]);
                    int aa = a4 + 2 * p, dd = d4 + j;
                    if (s == 0) { S.accS[aa][dd] = lo; S.accS[aa + 1][dd] = hi; }
                    else        { S.accS[aa][dd] += lo; S.accS[aa + 1][dd] += hi; }
                }
        }
    }
    __syncthreads();
    for (int idx = tid; idx < 1024; idx += 256) {
        int aa = idx >> 5, dd = idx & 31;
        atomicAdd(&g_acc[(a0 + aa) * 32 + dd], S.accS[aa][dd]);
    }
}

// ---------------- k7b: epilogue ----------------
__global__ void k7b_epilogue(float* __restrict__ out) {
    int idx = blockIdx.x * 256 + threadIdx.x;
    int n = idx >> 5, d = idx & 31;
    float acc = g_acc[idx];
    const float* r1 = g_r1 + n * 16;
    const float* c2 = g_c2 + n * 16;
    const float* wb = g_XW2b + n * 512 + d;
    const float* wa = g_XW2a + n * 512 + d;
#pragma unroll
    for (int t = 0; t < 16; t++) acc += r1[t] * wb[t * 32] + c2[t] * wa[t * 32];
    out[idx] = fmaxf(acc, 0.2f * acc);
}

// ---------------- launch ----------------
extern "C" void kernel_launch(void* const* d_in, const int* in_sizes, int n_in,
                              void* d_out, int out_size) {
    const float* x   = (const float*)d_in[0];
    const float* adj = (const float*)d_in[1];
    const float* W1  = (const float*)d_in[2];
    const float* W2  = (const float*)d_in[3];
    const float* W3  = (const float*)d_in[4];
    float* out = (float*)d_out;
    (void)in_sizes; (void)n_in; (void)out_size;

    cudaFuncSetAttribute(k7_fused, cudaFuncAttributeMaxDynamicSharedMemorySize,
                         (int)sizeof(K7S));

    k1_precompute<<<128, 256>>>(x, W1, W2, W3);
    k2_logits<<<dim3(16, 16), 512>>>(adj);
    k5_softmax<<<1024, 256>>>();
    k7_fused<<<dim3(16, 16, 2), 256, sizeof(K7S)>>>(adj);
    k7b_epilogue<<<64, 256>>>(out);
}